// round 14
// baseline (speedup 1.0000x reference)
#include <cuda_runtime.h>
#include <cuda_bf16.h>
#include <cstdint>

// Shapes (fixed): B=2048, V=256, T=11, K=8, N=8, H=255, K*H=2040
// x_unfolded: (B, V, T, K) fp32 exact one-hot along V (184.5 MB)
// out: (B, 2, T) fp32
//
// Collapse: out[b,o,t] = out_b[o] + sum_k LUT[o][k][ids[b,t,k]]
//
// Persistent-block cp.async pipeline:
//   304 blocks (2/SM), each streams ~6.7 slabs as 44KB half-slab chunks
//   through a 2-buffer cp.async.cg pipeline. Each thread copies and consumes
//   ITS OWN bytes -> no cross-thread buffer hazards. LUT built by blocks
//   0..127 (overlapped with first chunk transfer), then cached in smem.

#define VV 256
#define TT 11
#define KK 8
#define NN 8
#define HH 255
#define KH 2040
#define NSLAB 2048
#define SLAB4 5632        // float4 per slab
#define HALF4 2816        // float4 per half-slab chunk
#define GRID 304
#define LUTB 128

__device__ float d_LUT[2 * KK * VV];   // 16 KB
__device__ int   d_count = 0;
__device__ int   d_done  = 0;

// dynamic smem layout (bytes):
//   [0, 90112)        two 45056B chunk buffers
//   [90112, 106496)   LUT: 4096 floats, [o][k][v]
//   [106496, 106672)  acc: [2 parity][2 o][11 t] floats
#define SM_BUFSZ 45056
#define SM_LUT   90112
#define SM_ACC   106496
#define SM_TOTAL 106848

__device__ __forceinline__ void cp16(uint32_t s, const void* g) {
    asm volatile("cp.async.cg.shared.global [%0], [%1], 16;\n"
                 :: "r"(s), "l"(g) : "memory");
}

__global__ void __launch_bounds__(256, 2) fused_kernel(
    const float4* __restrict__ x,    // (B, V, T, K)
    const float*  __restrict__ sw,   // (N, V, K)
    const float*  __restrict__ hw,   // (K*H, N)
    const float*  __restrict__ ow,   // (2, K*H)
    const float*  __restrict__ ob,   // (2,)
    float*        __restrict__ out)  // (B, 2, T)
{
    extern __shared__ char smem[];
    float* s_lut = (float*)(smem + SM_LUT);
    float* s_acc = (float*)(smem + SM_ACC);   // parity*22 + o*11 + t

    const int tid  = threadIdx.x;
    const int bid  = blockIdx.x;
    const int lane = tid & 31;
    const int wid  = tid >> 5;

    uint32_t smem_u32;
    asm("{ .reg .u64 t; cvta.to.shared.u64 t, %1; cvt.u32.u64 %0, t; }"
        : "=r"(smem_u32) : "l"(smem));

    if (tid < 44) s_acc[tid] = 0.0f;   // both parities

    const int nslabs  = (NSLAB - 1 - bid) / GRID + 1;
    const int nchunks = nslabs * 2;

    // ---- prologue: prefetch chunk 0 (overlaps LUT build + poll) ----
    {
        const float4* src = x + (size_t)bid * SLAB4 + tid;  // (slab=bid, half 0)
        uint32_t dst = smem_u32 + tid * 16;
#pragma unroll
        for (int j = 0; j < 11; j++)
            cp16(dst + j * 4096, src + j * 256);
        asm volatile("cp.async.commit_group;\n" ::: "memory");
    }

    // ---- LUT build (blocks 0..127): 8 warps x 2 (k,v) pairs ----
    if (bid < LUTB) {
#pragma unroll
        for (int pp = 0; pp < 2; pp++) {
            int p = bid * 16 + wid * 2 + pp;   // 0..2047
            int k = p >> 8, v = p & 255;
            float s[NN];
#pragma unroll
            for (int n = 0; n < NN; n++)
                s[n] = fmaxf(sw[n * (VV * KK) + v * KK + k], 0.0f);
            float a0 = 0.0f, a1 = 0.0f;
            for (int h = lane; h < HH; h += 32) {
                int c = k * HH + h;
                const float4* hr = (const float4*)(hw + c * NN);
                float4 h0 = hr[0], h1 = hr[1];
                float t = h0.x*s[0] + h0.y*s[1] + h0.z*s[2] + h0.w*s[3]
                        + h1.x*s[4] + h1.y*s[5] + h1.z*s[6] + h1.w*s[7];
                t = fmaxf(t, 0.0f);
                a0 += ow[c] * t;
                a1 += ow[KH + c] * t;
            }
#pragma unroll
            for (int o = 16; o; o >>= 1) {
                a0 += __shfl_xor_sync(0xffffffffu, a0, o);
                a1 += __shfl_xor_sync(0xffffffffu, a1, o);
            }
            if (lane == 0) {
                d_LUT[k * VV + v]           = a0;
                d_LUT[KK * VV + k * VV + v] = a1;
            }
        }
        __syncthreads();
        if (tid == 0) { __threadfence(); atomicAdd(&d_count, 1); }
    }

    // ---- wait for full LUT (producers all resident), cache in smem ----
    if (tid == 0) {
        while (*(volatile int*)&d_count < LUTB) { }
    }
    __syncthreads();
    __threadfence();   // acquire
    {
        const float4* lg = (const float4*)d_LUT;
        float4*       ls = (float4*)s_lut;
#pragma unroll
        for (int j = 0; j < 4; j++)
            ls[tid + j * 256] = lg[tid + j * 256];
    }
    __syncthreads();

    const float ob0 = ob[0], ob1 = ob[1];

    // ---- main pipeline over chunks ----
    for (int c = 0; c < nchunks; c++) {
        if (c + 1 < nchunks) {
            int slab = bid + ((c + 1) >> 1) * GRID;
            int half = (c + 1) & 1;
            const float4* src = x + (size_t)slab * SLAB4 + half * HALF4 + tid;
            uint32_t dst = smem_u32 + ((c + 1) & 1) * SM_BUFSZ + tid * 16;
#pragma unroll
            for (int j = 0; j < 11; j++)
                cp16(dst + j * 4096, src + j * 256);
            asm volatile("cp.async.commit_group;\n" ::: "memory");
            asm volatile("cp.async.wait_group 1;\n" ::: "memory");
        } else {
            asm volatile("cp.async.wait_group 0;\n" ::: "memory");
        }

        // consume chunk c (thread-private bytes only)
        const int   half = c & 1;
        const int   par  = (c >> 1) & 1;
        const char* buf  = smem + (c & 1) * SM_BUFSZ;
        float*      acc  = s_acc + par * 22;
#pragma unroll
        for (int j = 0; j < 11; j++) {
            const uint4 q = *(const uint4*)(buf + tid * 16 + j * 4096);
            if (q.x | q.y | q.z | q.w) {
                int e0 = (half * HALF4 + tid + j * 256) * 4;
                uint32_t w4[4] = {q.x, q.y, q.z, q.w};
#pragma unroll
                for (int qq = 0; qq < 4; qq++) {
                    if (w4[qq]) {
                        int e  = e0 + qq;
                        int v  = e / (TT * KK);
                        int rr = e - v * (TT * KK);
                        int t  = rr >> 3, k = rr & 7;
                        float val = __uint_as_float(w4[qq]);
                        atomicAdd(&acc[t],      val * s_lut[k * VV + v]);
                        atomicAdd(&acc[11 + t], val * s_lut[KK * VV + k * VV + v]);
                    }
                }
            }
        }

        if (half == 1) {   // slab finished (uniform branch)
            int slab = bid + (c >> 1) * GRID;
            __syncthreads();                     // acc complete
            if (tid < 22) {
                int o = tid / 11, t = tid - o * 11;
                out[((size_t)slab * 2 + o) * TT + t] = acc[o * 11 + t] + (o ? ob1 : ob0);
                acc[tid] = 0.0f;   // reused 2 slabs later; ordered by next slab's sync
            }
        }
    }

    // ---- counter reset for graph-replay determinism ----
    __syncthreads();
    if (tid == 0) {
        __threadfence();
        if (atomicAdd(&d_done, 1) == GRID - 1) {
            d_count = 0;
            d_done  = 0;
            __threadfence();
        }
    }
}

extern "C" void kernel_launch(void* const* d_in, const int* in_sizes, int n_in,
                              void* d_out, int out_size)
{
    const float* x  = (const float*)d_in[0];  // (B, V, T, K)
    const float* sw = (const float*)d_in[1];  // (N, V, K)
    const float* hw = (const float*)d_in[2];  // (K*H, N)
    const float* ow = (const float*)d_in[3];  // (2, K*H)
    const float* ob = (const float*)d_in[4];  // (2,)
    float* out = (float*)d_out;               // (B, 2, T)
    (void)in_sizes; (void)n_in; (void)out_size;

    cudaFuncSetAttribute(fused_kernel,
                         cudaFuncAttributeMaxDynamicSharedMemorySize, SM_TOTAL);
    fused_kernel<<<GRID, 256, SM_TOTAL>>>((const float4*)x, sw, hw, ow, ob, out);
}